// round 1
// baseline (speedup 1.0000x reference)
#include <cuda_runtime.h>

// Problem dims (fixed by the dataset)
#define BB 256    // batch
#define FF 2048   // features
#define HH 512    // hidden
#define CC 512    // classes
#define EE 8      // experts
#define HH2 256   // hidden/2

// Scratch (allocation-free rule: __device__ globals)
__device__ float g_shared[BB * HH];                       // [B, H]   2 MB... 512KB
__device__ float g_h[(size_t)BB * CC * HH2];              // [B, C, Hh] 128 MB

// ---------------------------------------------------------------------------
// Kernel A: shared = relu(features @ Ws + bs)   [256,2048]x[2048,512]
// 32x32 tiles, 256 threads, 2x2 per thread. grid (8,16).
// ---------------------------------------------------------------------------
__global__ void shared_gemm(const float* __restrict__ feat,
                            const float* __restrict__ Ws,
                            const float* __restrict__ bs) {
    __shared__ float As[32][33];
    __shared__ float Bs[32][33];
    const int tid = threadIdx.x;
    const int tx = tid & 15, ty = tid >> 4;
    const int m0 = blockIdx.x * 32, n0 = blockIdx.y * 32;

    float acc00 = 0.f, acc01 = 0.f, acc10 = 0.f, acc11 = 0.f;

    const int kk = tid & 31;
    const int r  = tid >> 5;   // 0..7

    for (int k0 = 0; k0 < FF; k0 += 32) {
#pragma unroll
        for (int i = 0; i < 4; i++)
            As[r + 8 * i][kk] = feat[(size_t)(m0 + r + 8 * i) * FF + k0 + kk];
#pragma unroll
        for (int i = 0; i < 4; i++)
            Bs[r + 8 * i][kk] = Ws[(size_t)(k0 + r + 8 * i) * HH + n0 + kk];
        __syncthreads();
#pragma unroll
        for (int k = 0; k < 32; k++) {
            float a0 = As[ty * 2 + 0][k];
            float a1 = As[ty * 2 + 1][k];
            float b0 = Bs[k][tx * 2 + 0];
            float b1 = Bs[k][tx * 2 + 1];
            acc00 += a0 * b0; acc01 += a0 * b1;
            acc10 += a1 * b0; acc11 += a1 * b1;
        }
        __syncthreads();
    }
    const int m = m0 + ty * 2, n = n0 + tx * 2;
    float bv0 = bs[n], bv1 = bs[n + 1];
    g_shared[(m + 0) * HH + n + 0] = fmaxf(acc00 + bv0, 0.f);
    g_shared[(m + 0) * HH + n + 1] = fmaxf(acc01 + bv1, 0.f);
    g_shared[(m + 1) * HH + n + 0] = fmaxf(acc10 + bv0, 0.f);
    g_shared[(m + 1) * HH + n + 1] = fmaxf(acc11 + bv1, 0.f);
}

// ---------------------------------------------------------------------------
// Kernel B (dominant): per class c, h = relu(shared @ W1[c] + b1[c])
//   M=256 (B), N=256 (Hh), K=512 (H), batched over C=512.
// Block tile 128x128, Ktile 16, 256 threads, 8x8 per thread.
// grid (2, 2, 512).
// ---------------------------------------------------------------------------
__global__ void __launch_bounds__(256, 2)
gate1_gemm(const float* __restrict__ W1, const float* __restrict__ b1) {
    __shared__ float As[128][17];   // [m][k], padded
    __shared__ float Bs[16][128];   // [k][n]

    const int c  = blockIdx.z;
    const int m0 = blockIdx.x * 128;   // B dim
    const int n0 = blockIdx.y * 128;   // Hh dim
    const float* __restrict__ W1c = W1 + (size_t)c * HH * HH2;

    const int tid = threadIdx.x;
    const int tx = tid & 15, ty = tid >> 4;

    float acc[8][8];
#pragma unroll
    for (int i = 0; i < 8; i++)
#pragma unroll
        for (int j = 0; j < 8; j++) acc[i][j] = 0.f;

    const int akk = tid & 15;        // A load: k within tile
    const int ar0 = tid >> 4;        // A load: row base 0..15
    const int bn  = tid & 127;       // B load: n within tile
    const int bk0 = tid >> 7;        // B load: k base 0..1

    for (int k0 = 0; k0 < HH; k0 += 16) {
#pragma unroll
        for (int i = 0; i < 8; i++)
            As[ar0 + 16 * i][akk] =
                g_shared[(size_t)(m0 + ar0 + 16 * i) * HH + k0 + akk];
#pragma unroll
        for (int i = 0; i < 8; i++)
            Bs[bk0 + 2 * i][bn] =
                W1c[(size_t)(k0 + bk0 + 2 * i) * HH2 + n0 + bn];
        __syncthreads();

#pragma unroll
        for (int k = 0; k < 16; k++) {
            float a[8];
#pragma unroll
            for (int i = 0; i < 8; i++) a[i] = As[ty * 8 + i][k];
            float4 bv0 = *(const float4*)&Bs[k][tx * 8 + 0];
            float4 bv1 = *(const float4*)&Bs[k][tx * 8 + 4];
            float b[8] = {bv0.x, bv0.y, bv0.z, bv0.w, bv1.x, bv1.y, bv1.z, bv1.w};
#pragma unroll
            for (int i = 0; i < 8; i++)
#pragma unroll
                for (int j = 0; j < 8; j++)
                    acc[i][j] += a[i] * b[j];
        }
        __syncthreads();
    }

    // Epilogue: + b1, relu, store h[b][c][k]
    const int n = n0 + tx * 8;
    float bias[8];
#pragma unroll
    for (int j = 0; j < 8; j++) bias[j] = b1[c * HH2 + n + j];
#pragma unroll
    for (int i = 0; i < 8; i++) {
        const int m = m0 + ty * 8 + i;
        float* dst = &g_h[((size_t)m * CC + c) * HH2 + n];
        float4 v0, v1;
        v0.x = fmaxf(acc[i][0] + bias[0], 0.f);
        v0.y = fmaxf(acc[i][1] + bias[1], 0.f);
        v0.z = fmaxf(acc[i][2] + bias[2], 0.f);
        v0.w = fmaxf(acc[i][3] + bias[3], 0.f);
        v1.x = fmaxf(acc[i][4] + bias[4], 0.f);
        v1.y = fmaxf(acc[i][5] + bias[5], 0.f);
        v1.z = fmaxf(acc[i][6] + bias[6], 0.f);
        v1.w = fmaxf(acc[i][7] + bias[7], 0.f);
        *(float4*)(dst + 0) = v0;
        *(float4*)(dst + 4) = v1;
    }
}

// ---------------------------------------------------------------------------
// Kernel C: logits[b][c][e] = h[b][c][:] @ W2[c] + b2[c]; softmax over E=8.
// One warp per (b,c). Writes weights at [0, B*C*E), logits at [B*C*E, 2*B*C*E).
// ---------------------------------------------------------------------------
__global__ void gate2_softmax(const float* __restrict__ W2,
                              const float* __restrict__ b2,
                              float* __restrict__ out,
                              int write_logits) {
    const int gwarp = (blockIdx.x * blockDim.x + threadIdx.x) >> 5;
    const int lane  = threadIdx.x & 31;
    if (gwarp >= BB * CC) return;
    const int b = gwarp / CC, c = gwarp % CC;

    const float* __restrict__ hrow = &g_h[((size_t)b * CC + c) * HH2];
    const float* __restrict__ W2c  = W2 + (size_t)c * HH2 * EE;

    float acc[EE];
#pragma unroll
    for (int e = 0; e < EE; e++) acc[e] = 0.f;

#pragma unroll
    for (int j = 0; j < HH2 / 32; j++) {
        const int k = lane + 32 * j;
        const float hv = hrow[k];
        const float4* w = (const float4*)&W2c[(size_t)k * EE];
        float4 w0 = w[0], w1 = w[1];
        acc[0] += hv * w0.x; acc[1] += hv * w0.y;
        acc[2] += hv * w0.z; acc[3] += hv * w0.w;
        acc[4] += hv * w1.x; acc[5] += hv * w1.y;
        acc[6] += hv * w1.z; acc[7] += hv * w1.w;
    }
#pragma unroll
    for (int e = 0; e < EE; e++) {
#pragma unroll
        for (int off = 16; off > 0; off >>= 1)
            acc[e] += __shfl_xor_sync(0xffffffffu, acc[e], off);
    }
    if (lane == 0) {
        float logits[EE], mx = -1e30f;
#pragma unroll
        for (int e = 0; e < EE; e++) {
            logits[e] = acc[e] + b2[c * EE + e];
            mx = fmaxf(mx, logits[e]);
        }
        float w[EE], s = 0.f;
#pragma unroll
        for (int e = 0; e < EE; e++) { w[e] = expf(logits[e] - mx); s += w[e]; }
        const float inv = 1.f / s;
        const size_t base = ((size_t)b * CC + c) * EE;
#pragma unroll
        for (int e = 0; e < EE; e++) out[base + e] = w[e] * inv;
        if (write_logits) {
            const size_t lbase = (size_t)BB * CC * EE + base;
#pragma unroll
            for (int e = 0; e < EE; e++) out[lbase + e] = logits[e];
        }
    }
}

// ---------------------------------------------------------------------------
extern "C" void kernel_launch(void* const* d_in, const int* in_sizes, int n_in,
                              void* d_out, int out_size) {
    const float* feat = (const float*)d_in[0];
    const float* Ws   = (const float*)d_in[1];
    const float* bs   = (const float*)d_in[2];
    const float* W1   = (const float*)d_in[3];
    const float* b1   = (const float*)d_in[4];
    const float* W2   = (const float*)d_in[5];
    const float* b2   = (const float*)d_in[6];
    float* out = (float*)d_out;

    shared_gemm<<<dim3(BB / 32, HH / 32), 256>>>(feat, Ws, bs);
    gate1_gemm<<<dim3(2, 2, CC), 256>>>(W1, b1);

    const int write_logits = (out_size >= 2 * BB * CC * EE) ? 1 : 0;
    const int total_warps = BB * CC;                 // 131072
    const int threads = 256;                         // 8 warps/block
    const int blocks = (total_warps * 32 + threads - 1) / threads;
    gate2_softmax<<<blocks, threads>>>(W2, b2, out, write_logits);
}

// round 2
// speedup vs baseline: 3.3148x; 3.3148x over previous
#include <cuda_runtime.h>
#include <cstdint>

// Problem dims (fixed by dataset)
#define BB 256    // batch
#define FF 2048   // features
#define HH 512    // hidden
#define CC 512    // classes
#define EE 8      // experts
#define HH2 256   // hidden/2

// Scratch (allocation-free rule: __device__ globals)
__device__ float g_shared[BB * HH];          // [B,H] tf32-rounded activations
__device__ float g_logits[BB * CC * EE];     // [B,C,E] pre-softmax (no b2 yet)

// ---------------------------------------------------------------------------
// helpers
// ---------------------------------------------------------------------------
__device__ __forceinline__ unsigned f2tf32(float x) {
    unsigned u;
    asm("cvt.rna.tf32.f32 %0, %1;" : "=r"(u) : "f"(x));
    return u;
}
__device__ __forceinline__ unsigned smem_u32(const void* p) {
    return (unsigned)__cvta_generic_to_shared(p);
}
__device__ __forceinline__ void cp16(unsigned dst, const void* src) {
    asm volatile("cp.async.cg.shared.global [%0], [%1], 16;" :: "r"(dst), "l"(src));
}
#define CP_COMMIT() asm volatile("cp.async.commit_group;")

__device__ __forceinline__ void mma_tf32(float* d, const unsigned* a, const unsigned* b) {
    asm volatile(
        "mma.sync.aligned.m16n8k8.row.col.f32.tf32.tf32.f32 "
        "{%0,%1,%2,%3}, {%4,%5,%6,%7}, {%8,%9}, {%0,%1,%2,%3};"
        : "+f"(d[0]), "+f"(d[1]), "+f"(d[2]), "+f"(d[3])
        : "r"(a[0]), "r"(a[1]), "r"(a[2]), "r"(a[3]), "r"(b[0]), "r"(b[1]));
}

// ---------------------------------------------------------------------------
// Stage 1a: zero the shared-activation accumulator
// ---------------------------------------------------------------------------
__global__ void zero_shared() {
    int i = blockIdx.x * 256 + threadIdx.x;          // 32768 float4
    ((float4*)g_shared)[i] = make_float4(0.f, 0.f, 0.f, 0.f);
}

// ---------------------------------------------------------------------------
// Stage 1b: split-K GEMM  g_shared += feat @ Ws   (K chunks of 256, atomics)
// grid (8, 16, 8), 32x32 tile, 2x2/thread.
// ---------------------------------------------------------------------------
__global__ void gemm1_splitk(const float* __restrict__ feat,
                             const float* __restrict__ Ws) {
    __shared__ float As[32][33];
    __shared__ float Bsm[32][33];
    const int tid = threadIdx.x;
    const int tx = tid & 15, ty = tid >> 4;
    const int m0 = blockIdx.x * 32, n0 = blockIdx.y * 32;
    const int kbase = blockIdx.z * 256;

    float acc00 = 0.f, acc01 = 0.f, acc10 = 0.f, acc11 = 0.f;
    const int kk = tid & 31;
    const int r  = tid >> 5;   // 0..7

    for (int k0 = kbase; k0 < kbase + 256; k0 += 32) {
#pragma unroll
        for (int i = 0; i < 4; i++)
            As[r + 8 * i][kk] = feat[(size_t)(m0 + r + 8 * i) * FF + k0 + kk];
#pragma unroll
        for (int i = 0; i < 4; i++)
            Bsm[r + 8 * i][kk] = Ws[(size_t)(k0 + r + 8 * i) * HH + n0 + kk];
        __syncthreads();
#pragma unroll
        for (int k = 0; k < 32; k++) {
            float a0 = As[ty * 2 + 0][k];
            float a1 = As[ty * 2 + 1][k];
            float b0 = Bsm[k][tx * 2 + 0];
            float b1 = Bsm[k][tx * 2 + 1];
            acc00 += a0 * b0; acc01 += a0 * b1;
            acc10 += a1 * b0; acc11 += a1 * b1;
        }
        __syncthreads();
    }
    const int m = m0 + ty * 2, n = n0 + tx * 2;
    atomicAdd(&g_shared[(m + 0) * HH + n + 0], acc00);
    atomicAdd(&g_shared[(m + 0) * HH + n + 1], acc01);
    atomicAdd(&g_shared[(m + 1) * HH + n + 0], acc10);
    atomicAdd(&g_shared[(m + 1) * HH + n + 1], acc11);
}

// ---------------------------------------------------------------------------
// Stage 1c: bias + relu + tf32 round (in place)
// ---------------------------------------------------------------------------
__global__ void bias_relu_round(const float* __restrict__ bs) {
    int i = blockIdx.x * 256 + threadIdx.x;          // 32768 float4
    float4 v = ((float4*)g_shared)[i];
    int n = (i * 4) & (HH - 1);
    const float4 b = *(const float4*)&bs[n];
    v.x = __uint_as_float(f2tf32(fmaxf(v.x + b.x, 0.f)));
    v.y = __uint_as_float(f2tf32(fmaxf(v.y + b.y, 0.f)));
    v.z = __uint_as_float(f2tf32(fmaxf(v.z + b.z, 0.f)));
    v.w = __uint_as_float(f2tf32(fmaxf(v.w + b.w, 0.f)));
    ((float4*)g_shared)[i] = v;
}

// ---------------------------------------------------------------------------
// Stage 2+3 fused: per (c, m-tile of 128):
//   h = relu(shared @ W1[c] + b1[c])      [128 x 256]  (tf32 mma.sync)
//   logits[m, e] = h @ W2[c]              [128 x 8]    (SIMT epilogue)
// CTA tile M=128 N=256 K-step 32, 8 warps (2 m x 4 n), warp tile 64x64.
// grid (2, 512).
// ---------------------------------------------------------------------------
// dynamic SMEM layout (floats):
//   As double buf : [0, 9216)        (2 x 128 x 36)
//   Bs double buf : [9216, 26112)    (2 x 32 x 264)
//   hsm (overlay) : [0, 16512)       (128 x 129)
//   partial       : [16512, 18560)   (2 x 128 x 8)
//   W2s           : [26112, 28160)   (256 x 8)
//   b1s           : [28160, 28416)   (256)
#define SM_FLOATS 28416

__global__ void __launch_bounds__(256, 1)
gate_fused(const float* __restrict__ W1, const float* __restrict__ b1,
           const float* __restrict__ W2) {
    extern __shared__ float sm[];
    float* As      = sm;
    float* Bs      = sm + 9216;
    float* hsm     = sm;
    float* partial = sm + 16512;
    float* W2s     = sm + 26112;
    float* b1s     = sm + 28160;

    const int tid  = threadIdx.x;
    const int lane = tid & 31;
    const int wid  = tid >> 5;
    const int wm   = wid >> 2;          // 0..1
    const int wn   = wid & 3;           // 0..3
    const int g    = lane >> 2;         // 0..7
    const int t4   = lane & 3;          // 0..3
    const int c    = blockIdx.y;
    const int m0   = blockIdx.x * 128;
    const float* __restrict__ W1c = W1 + (size_t)c * HH * HH2;

    // preload per-class W2 and b1 into SMEM
#pragma unroll
    for (int i = 0; i < 8; i++)
        W2s[tid + 256 * i] = W2[(size_t)c * HH2 * EE + tid + 256 * i];
    b1s[tid] = b1[c * HH2 + tid];

    float acc[4][8][4];
#pragma unroll
    for (int mi = 0; mi < 4; mi++)
#pragma unroll
        for (int nj = 0; nj < 8; nj++)
#pragma unroll
            for (int v = 0; v < 4; v++) acc[mi][nj][v] = 0.f;

    auto load_tile = [&](int t, int buf) {
        const int k0 = t * 32;
        float* Ad = As + buf * 4608;
        float* Bd = Bs + buf * 8448;
#pragma unroll
        for (int i = 0; i < 4; i++) {
            int idx = tid + 256 * i;             // 0..1023
            int m = idx >> 3, k4 = idx & 7;
            cp16(smem_u32(Ad + m * 36 + k4 * 4),
                 g_shared + (size_t)(m0 + m) * HH + k0 + k4 * 4);
        }
#pragma unroll
        for (int i = 0; i < 8; i++) {
            int idx = tid + 256 * i;             // 0..2047
            int k = idx >> 6, n4 = idx & 63;
            cp16(smem_u32(Bd + k * 264 + n4 * 4),
                 W1c + (size_t)(k0 + k) * HH2 + n4 * 4);
        }
        CP_COMMIT();
    };

    load_tile(0, 0);

    for (int t = 0; t < 16; t++) {
        if (t + 1 < 16) {
            load_tile(t + 1, (t + 1) & 1);
            asm volatile("cp.async.wait_group 1;");
        } else {
            asm volatile("cp.async.wait_group 0;");
        }
        __syncthreads();

        const unsigned* AbU = (const unsigned*)(As + (t & 1) * 4608);
        const float*    Bb  = Bs + (t & 1) * 8448;

#pragma unroll
        for (int ks = 0; ks < 4; ks++) {
            const int kk = ks * 8;
            unsigned af[4][4];
#pragma unroll
            for (int mi = 0; mi < 4; mi++) {
                int r0 = (wm * 64 + mi * 16 + g) * 36 + kk + t4;
                af[mi][0] = AbU[r0];
                af[mi][1] = AbU[r0 + 8 * 36];
                af[mi][2] = AbU[r0 + 4];
                af[mi][3] = AbU[r0 + 8 * 36 + 4];
            }
            unsigned bf[8][2];
#pragma unroll
            for (int nj = 0; nj < 8; nj++) {
                int cidx = wn * 64 + nj * 8 + g;
                bf[nj][0] = f2tf32(Bb[(kk + t4) * 264 + cidx]);
                bf[nj][1] = f2tf32(Bb[(kk + 4 + t4) * 264 + cidx]);
            }
#pragma unroll
            for (int mi = 0; mi < 4; mi++)
#pragma unroll
                for (int nj = 0; nj < 8; nj++)
                    mma_tf32(acc[mi][nj], af[mi], bf[nj]);
        }
        __syncthreads();
    }

    // ---- fused epilogue: bias + relu -> SMEM; logits = h @ W2c ----
    float acc_e[8];
#pragma unroll
    for (int e = 0; e < 8; e++) acc_e[e] = 0.f;
    const int em = tid & 127, epart = tid >> 7;

#pragma unroll
    for (int half = 0; half < 2; half++) {
        if ((wn >> 1) == half) {
            const int nb = (wn & 1) * 64;
#pragma unroll
            for (int mi = 0; mi < 4; mi++) {
                int r0 = wm * 64 + mi * 16 + g;
#pragma unroll
                for (int nj = 0; nj < 8; nj++) {
                    int nl = nb + nj * 8 + 2 * t4;
                    int gn = half * 128 + nl;
                    hsm[r0 * 129 + nl]           = fmaxf(acc[mi][nj][0] + b1s[gn],     0.f);
                    hsm[r0 * 129 + nl + 1]       = fmaxf(acc[mi][nj][1] + b1s[gn + 1], 0.f);
                    hsm[(r0 + 8) * 129 + nl]     = fmaxf(acc[mi][nj][2] + b1s[gn],     0.f);
                    hsm[(r0 + 8) * 129 + nl + 1] = fmaxf(acc[mi][nj][3] + b1s[gn + 1], 0.f);
                }
            }
        }
        __syncthreads();
#pragma unroll 4
        for (int n = 0; n < 64; n++) {
            int nn = epart * 64 + n;
            float hv = hsm[em * 129 + nn];
            const float4* w = (const float4*)&W2s[(half * 128 + nn) * 8];
            float4 w0 = w[0], w1 = w[1];
            acc_e[0] += hv * w0.x; acc_e[1] += hv * w0.y;
            acc_e[2] += hv * w0.z; acc_e[3] += hv * w0.w;
            acc_e[4] += hv * w1.x; acc_e[5] += hv * w1.y;
            acc_e[6] += hv * w1.z; acc_e[7] += hv * w1.w;
        }
        __syncthreads();
    }

#pragma unroll
    for (int e = 0; e < 8; e++) partial[epart * 1024 + em * 8 + e] = acc_e[e];
    __syncthreads();
    if (tid < 128) {
        float4 p0 = *(float4*)&partial[tid * 8];
        float4 p1 = *(float4*)&partial[tid * 8 + 4];
        float4 q0 = *(float4*)&partial[1024 + tid * 8];
        float4 q1 = *(float4*)&partial[1024 + tid * 8 + 4];
        p0.x += q0.x; p0.y += q0.y; p0.z += q0.z; p0.w += q0.w;
        p1.x += q1.x; p1.y += q1.y; p1.z += q1.z; p1.w += q1.w;
        float* dst = &g_logits[((size_t)(m0 + tid) * CC + c) * EE];
        *(float4*)(dst + 0) = p0;
        *(float4*)(dst + 4) = p1;
    }
}

// ---------------------------------------------------------------------------
// Stage 4: + b2, softmax over E=8, write (weights, logits)
// ---------------------------------------------------------------------------
__global__ void softmax_out(const float* __restrict__ b2,
                            float* __restrict__ out, int write_logits) {
    const int idx = blockIdx.x * 256 + threadIdx.x;   // 0 .. B*C-1
    const int c = idx & (CC - 1);
    float lg[8];
    float4 l0 = *(const float4*)&g_logits[(size_t)idx * 8];
    float4 l1 = *(const float4*)&g_logits[(size_t)idx * 8 + 4];
    lg[0] = l0.x; lg[1] = l0.y; lg[2] = l0.z; lg[3] = l0.w;
    lg[4] = l1.x; lg[5] = l1.y; lg[6] = l1.z; lg[7] = l1.w;
    float mx = -1e30f;
#pragma unroll
    for (int e = 0; e < 8; e++) { lg[e] += b2[c * EE + e]; mx = fmaxf(mx, lg[e]); }
    float w[8], s = 0.f;
#pragma unroll
    for (int e = 0; e < 8; e++) { w[e] = expf(lg[e] - mx); s += w[e]; }
    const float inv = 1.f / s;
    const size_t base = (size_t)idx * 8;
#pragma unroll
    for (int e = 0; e < 8; e++) out[base + e] = w[e] * inv;
    if (write_logits) {
        const size_t lbase = (size_t)BB * CC * EE + base;
#pragma unroll
        for (int e = 0; e < 8; e++) out[lbase + e] = lg[e];
    }
}

// ---------------------------------------------------------------------------
extern "C" void kernel_launch(void* const* d_in, const int* in_sizes, int n_in,
                              void* d_out, int out_size) {
    const float* feat = (const float*)d_in[0];
    const float* Ws   = (const float*)d_in[1];
    const float* bs   = (const float*)d_in[2];
    const float* W1   = (const float*)d_in[3];
    const float* b1   = (const float*)d_in[4];
    const float* W2   = (const float*)d_in[5];
    const float* b2   = (const float*)d_in[6];
    float* out = (float*)d_out;

    zero_shared<<<128, 256>>>();
    gemm1_splitk<<<dim3(8, 16, 8), 256>>>(feat, Ws);
    bias_relu_round<<<128, 256>>>(bs);

    cudaFuncSetAttribute(gate_fused, cudaFuncAttributeMaxDynamicSharedMemorySize,
                         SM_FLOATS * 4);
    gate_fused<<<dim3(2, CC), 256, SM_FLOATS * 4>>>(W1, b1, W2);

    const int write_logits = (out_size >= 2 * BB * CC * EE) ? 1 : 0;
    softmax_out<<<BB * CC / 256, 256>>>(b2, out, write_logits);
}

// round 5
// speedup vs baseline: 3.5700x; 1.0770x over previous
#include <cuda_runtime.h>
#include <cstdint>

#define BB 256
#define FF 2048
#define HH 512
#define CC 512
#define EE 8
#define HH2 256
#define BCE (BB * CC * EE)

__device__ float g_shared[BB * HH];   // [B,H] tf32-rounded activations

// ---------------------------------------------------------------------------
// helpers
// ---------------------------------------------------------------------------
__device__ __forceinline__ unsigned f2tf32(float x) {
    unsigned u; asm("cvt.rna.tf32.f32 %0, %1;" : "=r"(u) : "f"(x)); return u;
}
__device__ __forceinline__ unsigned smem_u32(const void* p) {
    return (unsigned)__cvta_generic_to_shared(p);
}
__device__ __forceinline__ void cp16(unsigned dst, const void* src) {
    asm volatile("cp.async.cg.shared.global [%0], [%1], 16;" :: "r"(dst), "l"(src));
}
__device__ __forceinline__ void mma_tf32(float* d, const unsigned* a, const unsigned* b) {
    asm volatile(
        "mma.sync.aligned.m16n8k8.row.col.f32.tf32.tf32.f32 "
        "{%0,%1,%2,%3}, {%4,%5,%6,%7}, {%8,%9}, {%0,%1,%2,%3};"
        : "+f"(d[0]), "+f"(d[1]), "+f"(d[2]), "+f"(d[3])
        : "r"(a[0]), "r"(a[1]), "r"(a[2]), "r"(a[3]), "r"(b[0]), "r"(b[1]));
}

// ---------------------------------------------------------------------------
// Stage 1a: zero activation accumulator
// ---------------------------------------------------------------------------
__global__ void zero_shared() {
    int i = blockIdx.x * 256 + threadIdx.x;
    ((float4*)g_shared)[i] = make_float4(0.f, 0.f, 0.f, 0.f);
}

// ---------------------------------------------------------------------------
// Stage 1b: split-K SIMT GEMM  g_shared += feat @ Ws
// 64x64 tiles, 4x4/thread, K slices of 256. grid (4, 8, 8).
// ---------------------------------------------------------------------------
__global__ void __launch_bounds__(256)
gemm1_splitk(const float* __restrict__ feat, const float* __restrict__ Ws) {
    __shared__ float As[64][33];
    __shared__ float Bs[32][64];
    const int tid = threadIdx.x;
    const int tx = tid & 15, ty = tid >> 4;
    const int m0 = blockIdx.x * 64, n0 = blockIdx.y * 64;
    const int kbase = blockIdx.z * 256;

    float acc[4][4];
#pragma unroll
    for (int i = 0; i < 4; i++)
#pragma unroll
        for (int j = 0; j < 4; j++) acc[i][j] = 0.f;

    const int am = tid >> 2, akq = tid & 3;
    const int bk = tid >> 3, bnq = tid & 7;

    for (int k0 = kbase; k0 < kbase + 256; k0 += 32) {
#pragma unroll
        for (int h = 0; h < 2; h++) {
            float4 v = *(const float4*)&feat[(size_t)(m0 + am) * FF + k0 + akq * 8 + h * 4];
            As[am][akq * 8 + h * 4 + 0] = v.x;
            As[am][akq * 8 + h * 4 + 1] = v.y;
            As[am][akq * 8 + h * 4 + 2] = v.z;
            As[am][akq * 8 + h * 4 + 3] = v.w;
        }
#pragma unroll
        for (int h = 0; h < 2; h++) {
            float4 v = *(const float4*)&Ws[(size_t)(k0 + bk) * HH + n0 + bnq * 8 + h * 4];
            *(float4*)&Bs[bk][bnq * 8 + h * 4] = v;
        }
        __syncthreads();
#pragma unroll 8
        for (int k = 0; k < 32; k++) {
            float4 b4 = *(const float4*)&Bs[k][tx * 4];
            float b[4] = {b4.x, b4.y, b4.z, b4.w};
#pragma unroll
            for (int i = 0; i < 4; i++) {
                float a = As[ty * 4 + i][k];
#pragma unroll
                for (int j = 0; j < 4; j++) acc[i][j] += a * b[j];
            }
        }
        __syncthreads();
    }
#pragma unroll
    for (int i = 0; i < 4; i++)
#pragma unroll
        for (int j = 0; j < 4; j++)
            atomicAdd(&g_shared[(m0 + ty * 4 + i) * HH + n0 + tx * 4 + j], acc[i][j]);
}

// ---------------------------------------------------------------------------
// Stage 1c: bias + relu + tf32 round (in place)
// ---------------------------------------------------------------------------
__global__ void bias_relu_round(const float* __restrict__ bs) {
    int i = blockIdx.x * 256 + threadIdx.x;
    float4 v = ((float4*)g_shared)[i];
    int n = (i * 4) & (HH - 1);
    const float4 b = *(const float4*)&bs[n];
    v.x = __uint_as_float(f2tf32(fmaxf(v.x + b.x, 0.f)));
    v.y = __uint_as_float(f2tf32(fmaxf(v.y + b.y, 0.f)));
    v.z = __uint_as_float(f2tf32(fmaxf(v.z + b.z, 0.f)));
    v.w = __uint_as_float(f2tf32(fmaxf(v.w + b.w, 0.f)));
    ((float4*)g_shared)[i] = v;
}

// ---------------------------------------------------------------------------
// Stage 2+3+4 fused (mma.sync tf32):
//   per CTA (c, m-tile 128): h = relu(shared @ W1c + b1c) [128x256],
//   logits = h @ W2c + b2c [128x8], softmax, write.
// 512 threads, warp grid 2m x 8n, warp tile 64x32, K-step 32. grid (2, 512).
// ---------------------------------------------------------------------------
// dynamic smem layout (bytes):
//   A0 [0,18432)  A1 [18432,36864)        128 x 36 floats each
//   B0 [36864,70656)  B1 [70656,104448)   32 x 264 floats each
//   b1s [104448,105472)                   256 floats
//   W2s [105472,113664)                   2048 floats
// epilogue overlays:
//   hsm     [0, 67584)     = 128 x 132 floats  (over A0,A1,B0-head)
//   partial [70656, 87040) = 4 x 128 x 8       (over B1)
#define OFF_A    0
#define OFF_B    36864
#define A_STRIDE 18432
#define B_STRIDE 33792
#define OFF_B1S  104448
#define OFF_W2S  105472
#define SMEM_BYTES 113664

__global__ void __launch_bounds__(512, 1)
gate_fused(const float* __restrict__ W1, const float* __restrict__ b1,
           const float* __restrict__ W2, const float* __restrict__ b2,
           float* __restrict__ out, int write_logits) {
    extern __shared__ char sm[];
    const uint32_t smb = smem_u32(sm);
    const int tid  = threadIdx.x;
    const int lane = tid & 31;
    const int wid  = tid >> 5;
    const int wm   = wid >> 3;           // 0..1  (m)
    const int wn   = wid & 7;            // 0..7  (n)
    const int g    = lane >> 2;          // 0..7
    const int t4   = lane & 3;           // 0..3
    const int c    = blockIdx.y;
    const int m0   = blockIdx.x * 128;
    const float* __restrict__ W1c = W1 + (size_t)c * HH * HH2;

    float* b1s = (float*)(sm + OFF_B1S);
    float* W2s = (float*)(sm + OFF_W2S);
    if (tid < 256) b1s[tid] = b1[c * HH2 + tid];

    float acc[4][4][4];
#pragma unroll
    for (int mi = 0; mi < 4; mi++)
#pragma unroll
        for (int nj = 0; nj < 4; nj++)
#pragma unroll
            for (int v = 0; v < 4; v++) acc[mi][nj][v] = 0.f;

    auto load_tile = [&](int t, int buf) {
        const int k0 = t * 32;
        const uint32_t abase = smb + OFF_A + buf * A_STRIDE;
        const uint32_t bbase = smb + OFF_B + buf * B_STRIDE;
#pragma unroll
        for (int i = 0; i < 2; i++) {                 // A: 1024 x 16B
            int idx = tid + 512 * i;
            int m = idx >> 3, w = idx & 7;
            cp16(abase + (uint32_t)(m * 144 + w * 16),
                 g_shared + (size_t)(m0 + m) * HH + k0 + w * 4);
        }
#pragma unroll
        for (int i = 0; i < 4; i++) {                 // B: 2048 x 16B
            int idx = tid + 512 * i;
            int k = idx >> 6, n4 = idx & 63;
            cp16(bbase + (uint32_t)(k * 1056 + n4 * 16),
                 W1c + (size_t)(k0 + k) * HH2 + n4 * 4);
        }
        asm volatile("cp.async.commit_group;");
    };

    load_tile(0, 0);

    const int colb = wn * 32 + g;
    for (int t = 0; t < 16; t++) {
        const int buf = t & 1;
        if (t + 1 < 16) {
            load_tile(t + 1, (t + 1) & 1);
            asm volatile("cp.async.wait_group 1;");
        } else {
            asm volatile("cp.async.wait_group 0;");
        }
        __syncthreads();

        const unsigned* Ap = (const unsigned*)(sm + OFF_A + buf * A_STRIDE);
        const float*    Bp = (const float*)(sm + OFF_B + buf * B_STRIDE);

#pragma unroll
        for (int ks = 0; ks < 4; ks++) {
            const int kk = ks * 8;
            unsigned af[4][4];
#pragma unroll
            for (int mi = 0; mi < 4; mi++) {
                const int r0 = (wm * 64 + mi * 16 + g) * 36 + kk + t4;
                af[mi][0] = Ap[r0];
                af[mi][1] = Ap[r0 + 8 * 36];
                af[mi][2] = Ap[r0 + 4];
                af[mi][3] = Ap[r0 + 8 * 36 + 4];
            }
            unsigned bf[4][2];
#pragma unroll
            for (int nj = 0; nj < 4; nj++) {
                const int col = colb + nj * 8;
                bf[nj][0] = f2tf32(Bp[(kk + t4) * 264 + col]);
                bf[nj][1] = f2tf32(Bp[(kk + 4 + t4) * 264 + col]);
            }
#pragma unroll
            for (int mi = 0; mi < 4; mi++)
#pragma unroll
                for (int nj = 0; nj < 4; nj++)
                    mma_tf32(acc[mi][nj], af[mi], bf[nj]);
        }
        __syncthreads();
    }

    // stage W2 into smem
    {
        const float4* src = (const float4*)(W2 + (size_t)c * HH2 * EE);
        ((float4*)W2s)[tid] = src[tid];               // 512 x 16B = 2048 floats
    }

    // ---- epilogue: bias+relu via smem, logits = h @ W2 ----
    float* hsm = (float*)sm;                          // [128][132]
    const int em = tid & 127, epart = tid >> 7;       // row, col-quarter
    float acc_e[8];
#pragma unroll
    for (int e = 0; e < 8; e++) acc_e[e] = 0.f;

#pragma unroll
    for (int half = 0; half < 2; half++) {
        if ((wn >> 2) == half) {
#pragma unroll
            for (int mi = 0; mi < 4; mi++) {
                const int r0 = wm * 64 + mi * 16 + g;
#pragma unroll
                for (int nj = 0; nj < 4; nj++) {
                    const int nl = (wn & 3) * 32 + nj * 8 + 2 * t4;
                    const int gn = half * 128 + nl;
                    hsm[r0 * 132 + nl]           = fmaxf(acc[mi][nj][0] + b1s[gn],     0.f);
                    hsm[r0 * 132 + nl + 1]       = fmaxf(acc[mi][nj][1] + b1s[gn + 1], 0.f);
                    hsm[(r0 + 8) * 132 + nl]     = fmaxf(acc[mi][nj][2] + b1s[gn],     0.f);
                    hsm[(r0 + 8) * 132 + nl + 1] = fmaxf(acc[mi][nj][3] + b1s[gn + 1], 0.f);
                }
            }
        }
        __syncthreads();
#pragma unroll 4
        for (int n = 0; n < 32; n++) {
            const int nl = epart * 32 + n;
            const float hv = hsm[em * 132 + nl];
            const int gn = half * 128 + nl;
            const float4 w0 = *(const float4*)&W2s[gn * 8];
            const float4 w1 = *(const float4*)&W2s[gn * 8 + 4];
            acc_e[0] += hv * w0.x; acc_e[1] += hv * w0.y;
            acc_e[2] += hv * w0.z; acc_e[3] += hv * w0.w;
            acc_e[4] += hv * w1.x; acc_e[5] += hv * w1.y;
            acc_e[6] += hv * w1.z; acc_e[7] += hv * w1.w;
        }
        __syncthreads();
    }

    // combine 4 column-quarters, softmax, write
    float* partial = (float*)(sm + 70656);            // [4][128][8]
#pragma unroll
    for (int e = 0; e < 8; e++) partial[(epart * 128 + em) * 8 + e] = acc_e[e];
    __syncthreads();

    if (tid < 128) {
        float lg[8];
        const float4 b2lo = *(const float4*)(b2 + c * 8);
        const float4 b2hi = *(const float4*)(b2 + c * 8 + 4);
#pragma unroll
        for (int e = 0; e < 8; e++) lg[e] = 0.f;
#pragma unroll
        for (int p = 0; p < 4; p++) {
            const float4 q0 = *(float4*)&partial[(p * 128 + tid) * 8];
            const float4 q1 = *(float4*)&partial[(p * 128 + tid) * 8 + 4];
            lg[0] += q0.x; lg[1] += q0.y; lg[2] += q0.z; lg[3] += q0.w;
            lg[4] += q1.x; lg[5] += q1.y; lg[6] += q1.z; lg[7] += q1.w;
        }
        lg[0] += b2lo.x; lg[1] += b2lo.y; lg[2] += b2lo.z; lg[3] += b2lo.w;
        lg[4] += b2hi.x; lg[5] += b2hi.y; lg[6] += b2hi.z; lg[7] += b2hi.w;
        float mx = lg[0];
#pragma unroll
        for (int e = 1; e < 8; e++) mx = fmaxf(mx, lg[e]);
        float w[8], s = 0.f;
#pragma unroll
        for (int e = 0; e < 8; e++) { w[e] = expf(lg[e] - mx); s += w[e]; }
        const float inv = 1.f / s;
        const size_t base = ((size_t)(m0 + tid) * CC + c) * EE;
        *(float4*)(out + base)     = make_float4(w[0]*inv, w[1]*inv, w[2]*inv, w[3]*inv);
        *(float4*)(out + base + 4) = make_float4(w[4]*inv, w[5]*inv, w[6]*inv, w[7]*inv);
        if (write_logits) {
            *(float4*)(out + BCE + base)     = make_float4(lg[0], lg[1], lg[2], lg[3]);
            *(float4*)(out + BCE + base + 4) = make_float4(lg[4], lg[5], lg[6], lg[7]);
        }
    }
}

// ---------------------------------------------------------------------------
extern "C" void kernel_launch(void* const* d_in, const int* in_sizes, int n_in,
                              void* d_out, int out_size) {
    const float* feat = (const float*)d_in[0];
    const float* Ws   = (const float*)d_in[1];
    const float* bs   = (const float*)d_in[2];
    const float* W1   = (const float*)d_in[3];
    const float* b1   = (const float*)d_in[4];
    const float* W2   = (const float*)d_in[5];
    const float* b2   = (const float*)d_in[6];
    float* out = (float*)d_out;

    zero_shared<<<128, 256>>>();
    gemm1_splitk<<<dim3(4, 8, 8), 256>>>(feat, Ws);
    bias_relu_round<<<128, 256>>>(bs);

    cudaFuncSetAttribute(gate_fused, cudaFuncAttributeMaxDynamicSharedMemorySize,
                         SMEM_BYTES);
    const int write_logits = (out_size >= 2 * BCE) ? 1 : 0;
    gate_fused<<<dim3(2, CC), 512, SMEM_BYTES>>>(W1, b1, W2, b2, out, write_logits);
}